// round 2
// baseline (speedup 1.0000x reference)
#include <cuda_runtime.h>
#include <math.h>

#define Bb   32
#define Ss   577
#define Hh   1024
#define NH_  16
#define DH_  64
#define NTOK (Bb*Ss)          // 18464

// Scratch (allocation-free rule: __device__ globals)
__device__ float g_Q[(size_t)NTOK*Hh];   // head-major [B,NH,S,DH]
__device__ float g_K[(size_t)NTOK*Hh];
__device__ float g_V[(size_t)NTOK*Hh];
__device__ float g_C[(size_t)NTOK*Hh];   // token-major [B,S,H]

// ---------------------------------------------------------------------------
// SGEMM: out = A[N,1024] @ W[1024,1024]^T + bias  (torch Linear convention)
// MODE 0: write head-major  out[((b*NH+h)*S+s)*DH+d]
// MODE 1: write token-major out[n*1024+m]
// Block tile 128x128, K-tile 16, 8x8 per thread, 256 threads.
// ---------------------------------------------------------------------------
template<int MODE>
__global__ __launch_bounds__(256)
void sgemm_k(const float* __restrict__ A, const float* __restrict__ W,
             const float* __restrict__ bias, float* __restrict__ out, int N)
{
    __shared__ float As[16][128];
    __shared__ float Ws[16][128];

    const int tid = threadIdx.x;
    const int n0  = blockIdx.x * 128;
    const int m0  = blockIdx.y * 128;
    const int tr  = tid >> 4;       // 0..15 (row group)
    const int tc  = tid & 15;       // 0..15 (col group)
    const int lr  = tid >> 2;       // 0..63 load row
    const int lk  = (tid & 3) * 4;  // 0,4,8,12 load k

    float acc[8][8];
#pragma unroll
    for (int i = 0; i < 8; i++)
#pragma unroll
        for (int j = 0; j < 8; j++) acc[i][j] = 0.f;

    const int rA0 = n0 + lr, rA1 = n0 + lr + 64;
    const int rW0 = m0 + lr, rW1 = m0 + lr + 64;

    for (int k0 = 0; k0 < 1024; k0 += 16) {
        float4 a0 = make_float4(0.f,0.f,0.f,0.f);
        float4 a1 = make_float4(0.f,0.f,0.f,0.f);
        if (rA0 < N) a0 = *(const float4*)(A + (size_t)rA0*1024 + k0 + lk);
        if (rA1 < N) a1 = *(const float4*)(A + (size_t)rA1*1024 + k0 + lk);
        float4 w0 = *(const float4*)(W + (size_t)rW0*1024 + k0 + lk);
        float4 w1 = *(const float4*)(W + (size_t)rW1*1024 + k0 + lk);

        __syncthreads();
        As[lk+0][lr] = a0.x; As[lk+1][lr] = a0.y; As[lk+2][lr] = a0.z; As[lk+3][lr] = a0.w;
        As[lk+0][lr+64] = a1.x; As[lk+1][lr+64] = a1.y; As[lk+2][lr+64] = a1.z; As[lk+3][lr+64] = a1.w;
        Ws[lk+0][lr] = w0.x; Ws[lk+1][lr] = w0.y; Ws[lk+2][lr] = w0.z; Ws[lk+3][lr] = w0.w;
        Ws[lk+0][lr+64] = w1.x; Ws[lk+1][lr+64] = w1.y; Ws[lk+2][lr+64] = w1.z; Ws[lk+3][lr+64] = w1.w;
        __syncthreads();

#pragma unroll
        for (int kk = 0; kk < 16; kk++) {
            float4 av0 = *(const float4*)&As[kk][tr*8];
            float4 av1 = *(const float4*)&As[kk][tr*8+4];
            float4 bv0 = *(const float4*)&Ws[kk][tc*8];
            float4 bv1 = *(const float4*)&Ws[kk][tc*8+4];
            float a[8] = {av0.x,av0.y,av0.z,av0.w,av1.x,av1.y,av1.z,av1.w};
            float b[8] = {bv0.x,bv0.y,bv0.z,bv0.w,bv1.x,bv1.y,bv1.z,bv1.w};
#pragma unroll
            for (int i = 0; i < 8; i++)
#pragma unroll
                for (int j = 0; j < 8; j++) acc[i][j] = fmaf(a[i], b[j], acc[i][j]);
        }
    }

#pragma unroll
    for (int i = 0; i < 8; i++) {
        const int n = n0 + tr*8 + i;
        if (n >= N) continue;
        int bb = 0, ssx = 0;
        if (MODE == 0) { bb = n / Ss; ssx = n - bb*Ss; }
#pragma unroll
        for (int j = 0; j < 8; j++) {
            const int m = m0 + tc*8 + j;
            const float v = acc[i][j] + bias[m];
            if (MODE == 0) {
                const int h = m >> 6, d = m & 63;
                out[(((size_t)(bb*NH_ + h))*Ss + ssx)*DH_ + d] = v;
            } else {
                out[(size_t)n*1024 + m] = v;
            }
        }
    }
}

// ---------------------------------------------------------------------------
// Flash-style attention. Grid: (ceil(S/64)=10, B*NH=512). 256 threads.
// Q pre-scaled by 1/sqrt(DH); scores multiplied by mask (reference semantics).
// Smem: Qs 64x64 | KP 64x65 (K tile, reused as P tile) | Vs 64x64
// ---------------------------------------------------------------------------
__global__ __launch_bounds__(256)
void attn_k(const float* __restrict__ mask, float* __restrict__ ctx)
{
    extern __shared__ float sm[];
    float* Qs = sm;               // 4096
    float* KP = sm + 4096;        // 4160 (pitch 65)
    float* Vs = sm + 4096 + 4160; // 4096

    const int bh = blockIdx.y;
    const int b = bh >> 4, h = bh & 15;
    const int q0 = blockIdx.x * 64;
    const int tid = threadIdx.x;
    const int tr = tid >> 4, tc = tid & 15;

    const float* Qg = g_Q + (size_t)bh * Ss * DH_;
    const float* Kg = g_K + (size_t)bh * Ss * DH_;
    const float* Vg = g_V + (size_t)bh * Ss * DH_;
    const float scale = 0.125f;   // 1/sqrt(64)

    for (int i = tid; i < 4096; i += 256) {
        const int r = i >> 6, c = i & 63;
        const int q = q0 + r;
        Qs[i] = (q < Ss) ? Qg[(size_t)q*64 + c] * scale : 0.f;
    }

    float m_i[4], l_i[4], acc[4][4];
#pragma unroll
    for (int i = 0; i < 4; i++) {
        m_i[i] = -1e30f; l_i[i] = 0.f;
#pragma unroll
        for (int j = 0; j < 4; j++) acc[i][j] = 0.f;
    }

    for (int kt = 0; kt < 10; kt++) {
        const int k0 = kt * 64;
        __syncthreads();   // previous tile fully consumed
        for (int i = tid; i < 4096; i += 256) {
            const int r = i >> 6, c = i & 63;
            const int k = k0 + r;
            const float kv = (k < Ss) ? Kg[(size_t)k*64 + c] : 0.f;
            const float vv = (k < Ss) ? Vg[(size_t)k*64 + c] : 0.f;
            KP[r*65 + c] = kv;
            Vs[i] = vv;
        }
        __syncthreads();

        // scores s[i][j] = (Q*scale) . K
        float s[4][4];
#pragma unroll
        for (int i = 0; i < 4; i++)
#pragma unroll
            for (int j = 0; j < 4; j++) s[i][j] = 0.f;

#pragma unroll 8
        for (int d = 0; d < 64; d++) {
            float a[4], bb2[4];
#pragma unroll
            for (int i = 0; i < 4; i++) a[i]  = Qs[(tr*4+i)*64 + d];
#pragma unroll
            for (int j = 0; j < 4; j++) bb2[j] = KP[(tc*4+j)*65 + d];
#pragma unroll
            for (int i = 0; i < 4; i++)
#pragma unroll
                for (int j = 0; j < 4; j++) s[i][j] = fmaf(a[i], bb2[j], s[i][j]);
        }

        // multiplicative mask + key-padding
        float mk[4]; bool kok[4];
#pragma unroll
        for (int j = 0; j < 4; j++) {
            const int k = k0 + tc*4 + j;
            kok[j] = (k < Ss);
            mk[j] = kok[j] ? mask[b*Ss + k] : 0.f;
        }
#pragma unroll
        for (int i = 0; i < 4; i++)
#pragma unroll
            for (int j = 0; j < 4; j++)
                s[i][j] = kok[j] ? s[i][j]*mk[j] : -1e30f;

        // online softmax (row stats replicated across tc via 16-lane shuffles)
#pragma unroll
        for (int i = 0; i < 4; i++) {
            float tm = fmaxf(fmaxf(s[i][0], s[i][1]), fmaxf(s[i][2], s[i][3]));
#pragma unroll
            for (int o = 8; o >= 1; o >>= 1)
                tm = fmaxf(tm, __shfl_xor_sync(0xffffffffu, tm, o, 16));
            const float mn = fmaxf(m_i[i], tm);
            const float corr = __expf(m_i[i] - mn);
            float rs = 0.f;
#pragma unroll
            for (int j = 0; j < 4; j++) {
                const float p = __expf(s[i][j] - mn);
                s[i][j] = p; rs += p;
            }
#pragma unroll
            for (int o = 8; o >= 1; o >>= 1)
                rs += __shfl_xor_sync(0xffffffffu, rs, o, 16);
            l_i[i] = l_i[i]*corr + rs;
            m_i[i] = mn;
#pragma unroll
            for (int j = 0; j < 4; j++) acc[i][j] *= corr;
        }

        __syncthreads();   // all K reads done -> reuse KP as P
#pragma unroll
        for (int i = 0; i < 4; i++)
#pragma unroll
            for (int j = 0; j < 4; j++)
                KP[(tr*4+i)*65 + tc*4 + j] = s[i][j];
        __syncthreads();

        // acc += P @ V
#pragma unroll 8
        for (int kk = 0; kk < 64; kk++) {
            float pa[4];
#pragma unroll
            for (int i = 0; i < 4; i++) pa[i] = KP[(tr*4+i)*65 + kk];
            const float4 v4 = *(const float4*)&Vs[kk*64 + tc*4];
            const float vb[4] = {v4.x, v4.y, v4.z, v4.w};
#pragma unroll
            for (int i = 0; i < 4; i++)
#pragma unroll
                for (int j = 0; j < 4; j++) acc[i][j] = fmaf(pa[i], vb[j], acc[i][j]);
        }
    }

    // write ctx token-major [B,S,H]
#pragma unroll
    for (int i = 0; i < 4; i++) {
        const int q = q0 + tr*4 + i;
        if (q >= Ss) continue;
        const float inv = 1.f / l_i[i];
#pragma unroll
        for (int j = 0; j < 4; j++)
            ctx[((size_t)(b*Ss + q))*Hh + h*64 + tc*4 + j] = acc[i][j]*inv;
    }
}

// ---------------------------------------------------------------------------
extern "C" void kernel_launch(void* const* d_in, const int* in_sizes, int n_in,
                              void* d_out, int out_size)
{
    const float* X    = (const float*)d_in[0];
    const float* mask = (const float*)d_in[1];
    const float* Wq   = (const float*)d_in[2];
    const float* bq   = (const float*)d_in[3];
    const float* Wk   = (const float*)d_in[4];
    const float* bk   = (const float*)d_in[5];
    const float* Wv   = (const float*)d_in[6];
    const float* bv   = (const float*)d_in[7];
    const float* Wo   = (const float*)d_in[8];
    const float* bo   = (const float*)d_in[9];
    float* out = (float*)d_out;

    float *Qp, *Kp, *Vp, *Cp;
    cudaGetSymbolAddress((void**)&Qp, g_Q);
    cudaGetSymbolAddress((void**)&Kp, g_K);
    cudaGetSymbolAddress((void**)&Vp, g_V);
    cudaGetSymbolAddress((void**)&Cp, g_C);

    const dim3 gg((NTOK + 127) / 128, Hh / 128);
    sgemm_k<0><<<gg, 256>>>(X, Wq, bq, Qp, NTOK);
    sgemm_k<0><<<gg, 256>>>(X, Wk, bk, Kp, NTOK);
    sgemm_k<0><<<gg, 256>>>(X, Wv, bv, Vp, NTOK);

    const int smem = (4096 + 4160 + 4096) * (int)sizeof(float); // 49408 B
    cudaFuncSetAttribute(attn_k, cudaFuncAttributeMaxDynamicSharedMemorySize, smem);
    attn_k<<<dim3((Ss + 63) / 64, Bb * NH_), 256, smem>>>(mask, Cp);

    sgemm_k<1><<<gg, 256>>>(Cp, Wo, bo, out, NTOK);
}

// round 3
// speedup vs baseline: 1.0008x; 1.0008x over previous
#include <cuda_runtime.h>
#include <math.h>

#define Bb   32
#define Ss   577
#define Hh   1024
#define NH_  16
#define DH_  64
#define NTOK (Bb*Ss)          // 18464

// Scratch (allocation-free rule: __device__ globals)
__device__ float g_Q[(size_t)NTOK*Hh];   // head-major [B,NH,S,DH]
__device__ float g_K[(size_t)NTOK*Hh];
__device__ float g_V[(size_t)NTOK*Hh];
__device__ float g_C[(size_t)NTOK*Hh];   // token-major [B,S,H]

// ---------------------------------------------------------------------------
// SGEMM: out = A[N,1024] @ W[1024,1024]^T + bias  (torch Linear convention)
// MODE 0: write head-major  out[((b*NH+h)*S+s)*DH+d]
// MODE 1: write token-major out[n*1024+m]
// Block tile 128x128, K-tile 16, 8x8 per thread, 256 threads.
// ---------------------------------------------------------------------------
template<int MODE>
__global__ __launch_bounds__(256)
void sgemm_k(const float* __restrict__ A, const float* __restrict__ W,
             const float* __restrict__ bias, float* __restrict__ out, int N)
{
    __shared__ float As[16][128];
    __shared__ float Ws[16][128];

    const int tid = threadIdx.x;
    const int n0  = blockIdx.x * 128;
    const int m0  = blockIdx.y * 128;
    const int tr  = tid >> 4;       // 0..15 (row group)
    const int tc  = tid & 15;       // 0..15 (col group)
    const int lr  = tid >> 2;       // 0..63 load row
    const int lk  = (tid & 3) * 4;  // 0,4,8,12 load k

    float acc[8][8];
#pragma unroll
    for (int i = 0; i < 8; i++)
#pragma unroll
        for (int j = 0; j < 8; j++) acc[i][j] = 0.f;

    const int rA0 = n0 + lr, rA1 = n0 + lr + 64;
    const int rW0 = m0 + lr, rW1 = m0 + lr + 64;

    for (int k0 = 0; k0 < 1024; k0 += 16) {
        float4 a0 = make_float4(0.f,0.f,0.f,0.f);
        float4 a1 = make_float4(0.f,0.f,0.f,0.f);
        if (rA0 < N) a0 = *(const float4*)(A + (size_t)rA0*1024 + k0 + lk);
        if (rA1 < N) a1 = *(const float4*)(A + (size_t)rA1*1024 + k0 + lk);
        float4 w0 = *(const float4*)(W + (size_t)rW0*1024 + k0 + lk);
        float4 w1 = *(const float4*)(W + (size_t)rW1*1024 + k0 + lk);

        __syncthreads();
        As[lk+0][lr] = a0.x; As[lk+1][lr] = a0.y; As[lk+2][lr] = a0.z; As[lk+3][lr] = a0.w;
        As[lk+0][lr+64] = a1.x; As[lk+1][lr+64] = a1.y; As[lk+2][lr+64] = a1.z; As[lk+3][lr+64] = a1.w;
        Ws[lk+0][lr] = w0.x; Ws[lk+1][lr] = w0.y; Ws[lk+2][lr] = w0.z; Ws[lk+3][lr] = w0.w;
        Ws[lk+0][lr+64] = w1.x; Ws[lk+1][lr+64] = w1.y; Ws[lk+2][lr+64] = w1.z; Ws[lk+3][lr+64] = w1.w;
        __syncthreads();

#pragma unroll
        for (int kk = 0; kk < 16; kk++) {
            float4 av0 = *(const float4*)&As[kk][tr*8];
            float4 av1 = *(const float4*)&As[kk][tr*8+4];
            float4 bv0 = *(const float4*)&Ws[kk][tc*8];
            float4 bv1 = *(const float4*)&Ws[kk][tc*8+4];
            float a[8] = {av0.x,av0.y,av0.z,av0.w,av1.x,av1.y,av1.z,av1.w};
            float b[8] = {bv0.x,bv0.y,bv0.z,bv0.w,bv1.x,bv1.y,bv1.z,bv1.w};
#pragma unroll
            for (int i = 0; i < 8; i++)
#pragma unroll
                for (int j = 0; j < 8; j++) acc[i][j] = fmaf(a[i], b[j], acc[i][j]);
        }
    }

#pragma unroll
    for (int i = 0; i < 8; i++) {
        const int n = n0 + tr*8 + i;
        if (n >= N) continue;
        int bb = 0, ssx = 0;
        if (MODE == 0) { bb = n / Ss; ssx = n - bb*Ss; }
#pragma unroll
        for (int j = 0; j < 8; j++) {
            const int m = m0 + tc*8 + j;
            const float v = acc[i][j] + bias[m];
            if (MODE == 0) {
                const int h = m >> 6, d = m & 63;
                out[(((size_t)(bb*NH_ + h))*Ss + ssx)*DH_ + d] = v;
            } else {
                out[(size_t)n*1024 + m] = v;
            }
        }
    }
}

// ---------------------------------------------------------------------------
// Flash-style attention. Grid: (ceil(S/64)=10, B*NH=512). 256 threads.
// Q pre-scaled by 1/sqrt(DH); scores multiplied by mask (reference semantics).
// Smem: Qs 64x64 | KP 64x65 (K tile, reused as P tile) | Vs 64x64
// ---------------------------------------------------------------------------
__global__ __launch_bounds__(256)
void attn_k(const float* __restrict__ mask, float* __restrict__ ctx)
{
    extern __shared__ float sm[];
    float* Qs = sm;               // 4096
    float* KP = sm + 4096;        // 4160 (pitch 65)
    float* Vs = sm + 4096 + 4160; // 4096

    const int bh = blockIdx.y;
    const int b = bh >> 4, h = bh & 15;
    const int q0 = blockIdx.x * 64;
    const int tid = threadIdx.x;
    const int tr = tid >> 4, tc = tid & 15;

    const float* Qg = g_Q + (size_t)bh * Ss * DH_;
    const float* Kg = g_K + (size_t)bh * Ss * DH_;
    const float* Vg = g_V + (size_t)bh * Ss * DH_;
    const float scale = 0.125f;   // 1/sqrt(64)

    for (int i = tid; i < 4096; i += 256) {
        const int r = i >> 6, c = i & 63;
        const int q = q0 + r;
        Qs[i] = (q < Ss) ? Qg[(size_t)q*64 + c] * scale : 0.f;
    }

    float m_i[4], l_i[4], acc[4][4];
#pragma unroll
    for (int i = 0; i < 4; i++) {
        m_i[i] = -1e30f; l_i[i] = 0.f;
#pragma unroll
        for (int j = 0; j < 4; j++) acc[i][j] = 0.f;
    }

    for (int kt = 0; kt < 10; kt++) {
        const int k0 = kt * 64;
        __syncthreads();   // previous tile fully consumed
        for (int i = tid; i < 4096; i += 256) {
            const int r = i >> 6, c = i & 63;
            const int k = k0 + r;
            const float kv = (k < Ss) ? Kg[(size_t)k*64 + c] : 0.f;
            const float vv = (k < Ss) ? Vg[(size_t)k*64 + c] : 0.f;
            KP[r*65 + c] = kv;
            Vs[i] = vv;
        }
        __syncthreads();

        // scores s[i][j] = (Q*scale) . K
        float s[4][4];
#pragma unroll
        for (int i = 0; i < 4; i++)
#pragma unroll
            for (int j = 0; j < 4; j++) s[i][j] = 0.f;

#pragma unroll 8
        for (int d = 0; d < 64; d++) {
            float a[4], bb2[4];
#pragma unroll
            for (int i = 0; i < 4; i++) a[i]  = Qs[(tr*4+i)*64 + d];
#pragma unroll
            for (int j = 0; j < 4; j++) bb2[j] = KP[(tc*4+j)*65 + d];
#pragma unroll
            for (int i = 0; i < 4; i++)
#pragma unroll
                for (int j = 0; j < 4; j++) s[i][j] = fmaf(a[i], bb2[j], s[i][j]);
        }

        // multiplicative mask + key-padding
        float mk[4]; bool kok[4];
#pragma unroll
        for (int j = 0; j < 4; j++) {
            const int k = k0 + tc*4 + j;
            kok[j] = (k < Ss);
            mk[j] = kok[j] ? mask[b*Ss + k] : 0.f;
        }
#pragma unroll
        for (int i = 0; i < 4; i++)
#pragma unroll
            for (int j = 0; j < 4; j++)
                s[i][j] = kok[j] ? s[i][j]*mk[j] : -1e30f;

        // online softmax (row stats replicated across tc via 16-lane shuffles)
#pragma unroll
        for (int i = 0; i < 4; i++) {
            float tm = fmaxf(fmaxf(s[i][0], s[i][1]), fmaxf(s[i][2], s[i][3]));
#pragma unroll
            for (int o = 8; o >= 1; o >>= 1)
                tm = fmaxf(tm, __shfl_xor_sync(0xffffffffu, tm, o, 16));
            const float mn = fmaxf(m_i[i], tm);
            const float corr = __expf(m_i[i] - mn);
            float rs = 0.f;
#pragma unroll
            for (int j = 0; j < 4; j++) {
                const float p = __expf(s[i][j] - mn);
                s[i][j] = p; rs += p;
            }
#pragma unroll
            for (int o = 8; o >= 1; o >>= 1)
                rs += __shfl_xor_sync(0xffffffffu, rs, o, 16);
            l_i[i] = l_i[i]*corr + rs;
            m_i[i] = mn;
#pragma unroll
            for (int j = 0; j < 4; j++) acc[i][j] *= corr;
        }

        __syncthreads();   // all K reads done -> reuse KP as P
#pragma unroll
        for (int i = 0; i < 4; i++)
#pragma unroll
            for (int j = 0; j < 4; j++)
                KP[(tr*4+i)*65 + tc*4 + j] = s[i][j];
        __syncthreads();

        // acc += P @ V
#pragma unroll 8
        for (int kk = 0; kk < 64; kk++) {
            float pa[4];
#pragma unroll
            for (int i = 0; i < 4; i++) pa[i] = KP[(tr*4+i)*65 + kk];
            const float4 v4 = *(const float4*)&Vs[kk*64 + tc*4];
            const float vb[4] = {v4.x, v4.y, v4.z, v4.w};
#pragma unroll
            for (int i = 0; i < 4; i++)
#pragma unroll
                for (int j = 0; j < 4; j++) acc[i][j] = fmaf(pa[i], vb[j], acc[i][j]);
        }
    }

    // write ctx token-major [B,S,H]
#pragma unroll
    for (int i = 0; i < 4; i++) {
        const int q = q0 + tr*4 + i;
        if (q >= Ss) continue;
        const float inv = 1.f / l_i[i];
#pragma unroll
        for (int j = 0; j < 4; j++)
            ctx[((size_t)(b*Ss + q))*Hh + h*64 + tc*4 + j] = acc[i][j]*inv;
    }
}

// ---------------------------------------------------------------------------
extern "C" void kernel_launch(void* const* d_in, const int* in_sizes, int n_in,
                              void* d_out, int out_size)
{
    const float* X    = (const float*)d_in[0];
    const float* mask = (const float*)d_in[1];
    const float* Wq   = (const float*)d_in[2];
    const float* bq   = (const float*)d_in[3];
    const float* Wk   = (const float*)d_in[4];
    const float* bk   = (const float*)d_in[5];
    const float* Wv   = (const float*)d_in[6];
    const float* bv   = (const float*)d_in[7];
    const float* Wo   = (const float*)d_in[8];
    const float* bo   = (const float*)d_in[9];
    float* out = (float*)d_out;

    float *Qp, *Kp, *Vp, *Cp;
    cudaGetSymbolAddress((void**)&Qp, g_Q);
    cudaGetSymbolAddress((void**)&Kp, g_K);
    cudaGetSymbolAddress((void**)&Vp, g_V);
    cudaGetSymbolAddress((void**)&Cp, g_C);

    const dim3 gg((NTOK + 127) / 128, Hh / 128);
    sgemm_k<0><<<gg, 256>>>(X, Wq, bq, Qp, NTOK);
    sgemm_k<0><<<gg, 256>>>(X, Wk, bk, Kp, NTOK);
    sgemm_k<0><<<gg, 256>>>(X, Wv, bv, Vp, NTOK);

    const int smem = (4096 + 4160 + 4096) * (int)sizeof(float); // 49408 B
    cudaFuncSetAttribute(attn_k, cudaFuncAttributeMaxDynamicSharedMemorySize, smem);
    attn_k<<<dim3((Ss + 63) / 64, Bb * NH_), 256, smem>>>(mask, Cp);

    sgemm_k<1><<<gg, 256>>>(Cp, Wo, bo, out, NTOK);
}